// round 4
// baseline (speedup 1.0000x reference)
#include <cuda_runtime.h>
#include <cstdint>

#define Nn 8192
#define FOUT 64
#define GAT_ALPHA 0.2f
#define LOG2E 1.4426950408889634f
#define NJQ 8          // j splits
#define JW 1024        // j width per split
#define NCH 16         // chunks of 64 per split

// ---------------- scratch ----------------
__device__ float g_h[Nn * FOUT];
__device__ float g_ssrc[Nn];
__device__ float g_sdst[Nn];
__device__ float g_part[1024];
__device__ float g_gmax;
__device__ float g_o8[NJQ * Nn * FOUT];
__device__ float g_z8[NJQ * Nn];

// ---------------- helpers ----------------
__device__ __forceinline__ float lrelu(float x) { return fmaxf(x, GAT_ALPHA * x); }

__device__ __forceinline__ unsigned long long pack2(float x, float y) {
    unsigned long long r;
    asm("mov.b64 %0, {%1, %2};" : "=l"(r) : "f"(x), "f"(y));
    return r;
}
__device__ __forceinline__ float2 unpack2(unsigned long long v) {
    float2 f;
    asm("mov.b64 {%0, %1}, %2;" : "=f"(f.x), "=f"(f.y) : "l"(v));
    return f;
}
__device__ __forceinline__ unsigned long long ffma2(unsigned long long a,
                                                    unsigned long long b,
                                                    unsigned long long c) {
    unsigned long long d;
    asm("fma.rn.f32x2 %0, %1, %2, %3;" : "=l"(d) : "l"(a), "l"(b), "l"(c));
    return d;
}

// ---------------- kernel 1: h = input @ W ----------------
__global__ __launch_bounds__(256) void k_proj(const float* __restrict__ input,
                                              const float* __restrict__ Wm) {
    __shared__ float in_s[16 * 512];
    const int t = threadIdx.x;
    const int i0 = blockIdx.x * 16;
#pragma unroll
    for (int q = 0; q < 8; ++q) {
        int idx = q * 256 + t;
        int row = idx >> 7;
        int c4 = idx & 127;
        *(float4*)(in_s + row * 512 + c4 * 4) =
            *(const float4*)(input + (size_t)(i0 + row) * 512 + c4 * 4);
    }
    __syncthreads();
    const int f = t & 63;
    const int rg = t >> 6;
    float acc[4] = {0.f, 0.f, 0.f, 0.f};
    const float* ip = in_s + rg * 4 * 512;
    for (int k = 0; k < 512; k += 4) {
        float w0 = __ldg(Wm + (k + 0) * 64 + f);
        float w1 = __ldg(Wm + (k + 1) * 64 + f);
        float w2 = __ldg(Wm + (k + 2) * 64 + f);
        float w3 = __ldg(Wm + (k + 3) * 64 + f);
#pragma unroll
        for (int i = 0; i < 4; ++i) {
            float4 iv = *(const float4*)(ip + i * 512 + k);
            acc[i] = fmaf(iv.x, w0, acc[i]);
            acc[i] = fmaf(iv.y, w1, acc[i]);
            acc[i] = fmaf(iv.z, w2, acc[i]);
            acc[i] = fmaf(iv.w, w3, acc[i]);
        }
    }
#pragma unroll
    for (int i = 0; i < 4; ++i)
        g_h[(size_t)(i0 + rg * 4 + i) * 64 + f] = acc[i];
}

// ---------------- kernel 1b/1c: scores + global max ----------------
__global__ __launch_bounds__(256) void k_scores(const float* __restrict__ av) {
    __shared__ float sdm[8];
    const int t = threadIdx.x;
    const int w = t >> 5, l = t & 31;
    const int row = blockIdx.x * 8 + w;
    float v0 = g_h[(size_t)row * 64 + l];
    float v1 = g_h[(size_t)row * 64 + 32 + l];
    float ss = v0 * __ldg(av + l) + v1 * __ldg(av + 32 + l);
    float sd = v0 * __ldg(av + 64 + l) + v1 * __ldg(av + 96 + l);
#pragma unroll
    for (int o = 16; o; o >>= 1) {
        ss += __shfl_xor_sync(0xffffffffu, ss, o);
        sd += __shfl_xor_sync(0xffffffffu, sd, o);
    }
    if (l == 0) {
        g_ssrc[row] = ss;
        g_sdst[row] = sd;
        sdm[w] = sd;
    }
    __syncthreads();
    if (t == 0) {
        float m = sdm[0];
#pragma unroll
        for (int i = 1; i < 8; ++i) m = fmaxf(m, sdm[i]);
        g_part[blockIdx.x] = m;
    }
}

__global__ __launch_bounds__(1024) void k_max() {
    __shared__ float s[1024];
    const int t = threadIdx.x;
    s[t] = g_part[t];
    __syncthreads();
    for (int o = 512; o; o >>= 1) {
        if (t < o) s[t] = fmaxf(s[t], s[t + o]);
        __syncthreads();
    }
    if (t == 0) g_gmax = s[0];
}

// ---------------- kernel 2: attention, one j-eighth ----------------
// grid 1024 = 128 i-tiles x 8 j-splits. 64 threads, 64 rows, 16 chunks of 64 j.
// Thread tile: 8 rows (rg8 = t>>3) x 8 feats (fg = t&7, feats fg*4 and 32+fg*4).
// Per s-iter: 8 h + 8 p LDS.128 vs 128 FFMA2 -> crossbar and FMA pipe balanced.
__global__ __launch_bounds__(64, 6) void k_attn(const int* __restrict__ adj) {
    __shared__ float4 h_s4[64 * 16];   // [jj][f4], no swizzle needed
    __shared__ float4 p_s4[64 * 16];   // [r][j4 ^ (r>>3)]
    __shared__ float  sdL_s[64];
    __shared__ float2 c_s[64];
    __shared__ float  zrow_s[64];

    const int t = threadIdx.x;
    const int i_tile = blockIdx.x >> 3;
    const int jq = blockIdx.x & 7;
    const int i0 = i_tile * 64;
    const int jb = jq * JW;
    const int fg = t & 7;
    const int rg8 = t >> 3;            // 0..7

    if (t < 64) {
        float ss = g_ssrc[i0 + t];
        float m = lrelu(ss + g_gmax);
        c_s[t] = make_float2(LOG2E * ss, -LOG2E * m);
        zrow_s[t] = 0.f;
    }

    unsigned long long acc[8][4];
#pragma unroll
    for (int i = 0; i < 8; ++i)
#pragma unroll
        for (int k = 0; k < 4; ++k) acc[i][k] = 0ULL;
    float zp[8] = {0.f, 0.f, 0.f, 0.f, 0.f, 0.f, 0.f, 0.f};

    for (int c = 0; c < NCH; ++c) {
        const int j0 = c * 64;
        __syncthreads();               // prev GEMM done with tiles

        // ---- issue all adj loads for this chunk (MLP = 16) ----
        int4 abuf[8][2];
#pragma unroll
        for (int pp = 0; pp < 8; ++pp) {
            const int* ap = adj + (size_t)(i0 + pp * 8 + rg8) * Nn + jb + j0 + fg * 8;
            abuf[pp][0] = *(const int4*)(ap);
            abuf[pp][1] = *(const int4*)(ap + 4);
        }

        // ---- stage h tile (overlaps adj DRAM latency) ----
        {
            const float4* src = (const float4*)(g_h + (size_t)(jb + j0) * 64);
#pragma unroll
            for (int q = 0; q < 16; ++q) {
                int idx = q * 64 + t;              // 1024 float4
                h_s4[idx] = src[idx];
            }
        }
        if (t < 64) sdL_s[t] = LOG2E * g_sdst[jb + j0 + t];
        __syncthreads();               // sdL + h staged

        // ---- p-phase: rows pp*8+rg8, j cols fg*8..fg*8+7 ----
#pragma unroll
        for (int pp = 0; pp < 8; ++pp) {
            const int r = pp * 8 + rg8;
            const float2 cc = c_s[r];
            float z = 0.f;
#pragma unroll
            for (int hh = 0; hh < 2; ++hh) {
                int4 a = abuf[pp][hh];
                float4 sd = *(const float4*)&sdL_s[fg * 8 + hh * 4];
                float4 pv;
                {
                    float u = cc.x + sd.x;
                    float e = exp2f(fmaxf(u + cc.y, fmaf(GAT_ALPHA, u, cc.y)));
                    pv.x = (a.x > 0) ? e : 0.f;
                }
                {
                    float u = cc.x + sd.y;
                    float e = exp2f(fmaxf(u + cc.y, fmaf(GAT_ALPHA, u, cc.y)));
                    pv.y = (a.y > 0) ? e : 0.f;
                }
                {
                    float u = cc.x + sd.z;
                    float e = exp2f(fmaxf(u + cc.y, fmaf(GAT_ALPHA, u, cc.y)));
                    pv.z = (a.z > 0) ? e : 0.f;
                }
                {
                    float u = cc.x + sd.w;
                    float e = exp2f(fmaxf(u + cc.y, fmaf(GAT_ALPHA, u, cc.y)));
                    pv.w = (a.w > 0) ? e : 0.f;
                }
                z += (pv.x + pv.y) + (pv.z + pv.w);
                p_s4[r * 16 + ((fg * 2 + hh) ^ pp)] = pv;   // swizzle mask = r>>3 = pp
            }
            zp[pp] += z;
        }
        __syncthreads();               // p ready

        // ---- GEMM: acc[8 rows][8 feats] += p * h ----
#pragma unroll 2
        for (int s = 0; s < 16; ++s) {
            unsigned long long hl[4][2], hh2[4][2];
#pragma unroll
            for (int k = 0; k < 4; ++k) {
                const int jj = s * 4 + k;
                float4 hlo = h_s4[jj * 16 + fg];
                float4 hhi = h_s4[jj * 16 + 8 + fg];
                hl[k][0] = pack2(hlo.x, hlo.y);
                hl[k][1] = pack2(hlo.z, hlo.w);
                hh2[k][0] = pack2(hhi.x, hhi.y);
                hh2[k][1] = pack2(hhi.z, hhi.w);
            }
#pragma unroll
            for (int rr = 0; rr < 8; ++rr) {
                const int r = rg8 * 8 + rr;
                float4 pv = p_s4[r * 16 + (s ^ rg8)];
#pragma unroll
                for (int k = 0; k < 4; ++k) {
                    float pk = (k == 0) ? pv.x : (k == 1) ? pv.y
                             : (k == 2) ? pv.z : pv.w;
                    unsigned long long pp2 = pack2(pk, pk);
                    acc[rr][0] = ffma2(pp2, hl[k][0], acc[rr][0]);
                    acc[rr][1] = ffma2(pp2, hl[k][1], acc[rr][1]);
                    acc[rr][2] = ffma2(pp2, hh2[k][0], acc[rr][2]);
                    acc[rr][3] = ffma2(pp2, hh2[k][1], acc[rr][3]);
                }
            }
        }
    }

    // ---- z reduce + write partials ----
    __syncthreads();
#pragma unroll
    for (int pp = 0; pp < 8; ++pp)
        atomicAdd(&zrow_s[pp * 8 + rg8], zp[pp]);

    float* ob = g_o8 + (size_t)jq * Nn * 64;
#pragma unroll
    for (int rr = 0; rr < 8; ++rr) {
        const int r = rg8 * 8 + rr;
        float2 a0 = unpack2(acc[rr][0]);
        float2 a1 = unpack2(acc[rr][1]);
        float2 a2 = unpack2(acc[rr][2]);
        float2 a3 = unpack2(acc[rr][3]);
        *(float4*)(ob + (size_t)(i0 + r) * 64 + fg * 4) =
            make_float4(a0.x, a0.y, a1.x, a1.y);
        *(float4*)(ob + (size_t)(i0 + r) * 64 + 32 + fg * 4) =
            make_float4(a2.x, a2.y, a3.x, a3.y);
    }
    __syncthreads();
    if (t < 64) g_z8[jq * Nn + i0 + t] = zrow_s[t];
}

// ---------------- kernel 3: combine + normalize ----------------
__global__ __launch_bounds__(256) void k_norm(float* __restrict__ out) {
    const int idx = blockIdx.x * 256 + threadIdx.x;   // float4 index
    const int row = idx >> 4;
    const float4* o0 = (const float4*)g_o8;
    float4 o = make_float4(0.f, 0.f, 0.f, 0.f);
    float z = 0.f;
#pragma unroll
    for (int k = 0; k < NJQ; ++k) {
        float4 a = o0[(size_t)k * Nn * 16 + idx];
        o.x += a.x; o.y += a.y; o.z += a.z; o.w += a.w;
        z += g_z8[k * Nn + row];
    }
    float zi = 1.0f / z;
    o.x *= zi; o.y *= zi; o.z *= zi; o.w *= zi;
    ((float4*)out)[idx] = o;
}

// ---------------- launch ----------------
extern "C" void kernel_launch(void* const* d_in, const int* in_sizes, int n_in,
                              void* d_out, int out_size) {
    const float* input = (const float*)d_in[0];
    const int*   adj   = (const int*)d_in[1];
    const float* Wm    = (const float*)d_in[2];
    const float* av    = (const float*)d_in[3];
    float* out = (float*)d_out;

    // allow deep smem carveout for 6 CTAs/SM (idempotent; ignore errors)
    cudaFuncSetAttribute((const void*)k_attn,
                         cudaFuncAttributePreferredSharedMemoryCarveout, 100);

    k_proj<<<Nn / 16, 256>>>(input, Wm);
    k_scores<<<Nn / 8, 256>>>(av);
    k_max<<<1, 1024>>>();
    k_attn<<<128 * NJQ, 64>>>(adj);
    k_norm<<<512, 256>>>(out);
}

// round 6
// speedup vs baseline: 1.3148x; 1.3148x over previous
#include <cuda_runtime.h>
#include <cstdint>

#define Nn 8192
#define GAT_ALPHA 0.2f
#define LOG2E 1.4426950408889634f
#define NJQ 8
#define JW 1024
#define NCH 16

// ---------------- scratch ----------------
__device__ float g_h[Nn * 64];
__device__ float g_hT[64 * Nn];        // transposed, tf32-rounded
__device__ float g_ssrc[Nn];
__device__ float g_sdst[Nn];
__device__ float g_part[1024];
__device__ float g_gmax;
__device__ float g_o8[NJQ * Nn * 64];
__device__ float g_z8[NJQ * Nn];

// ---------------- helpers ----------------
__device__ __forceinline__ uint32_t f2tf32(float x) {
    uint32_t r;
    asm("cvt.rna.tf32.f32 %0, %1;" : "=r"(r) : "f"(x));
    return r;
}
__device__ __forceinline__ void mma_tf32(float* c, uint32_t a0, uint32_t a1,
                                         uint32_t a2, uint32_t a3,
                                         uint32_t b0, uint32_t b1) {
    asm volatile(
        "mma.sync.aligned.m16n8k8.row.col.f32.tf32.tf32.f32 "
        "{%0,%1,%2,%3}, {%4,%5,%6,%7}, {%8,%9}, {%0,%1,%2,%3};"
        : "+f"(c[0]), "+f"(c[1]), "+f"(c[2]), "+f"(c[3])
        : "r"(a0), "r"(a1), "r"(a2), "r"(a3), "r"(b0), "r"(b1));
}
// 5-bit bank swizzle: word index k in a 64-word row, keyed by row r.
__device__ __forceinline__ int swz(int k, int r) {
    return k ^ ((r & 3) << 3) ^ (((r >> 2) & 1) << 2);
}

// ---------------- kernel 1: h = input @ W ----------------
__global__ __launch_bounds__(256) void k_proj(const float* __restrict__ input,
                                              const float* __restrict__ Wm) {
    __shared__ float in_s[16 * 512];
    const int t = threadIdx.x;
    const int i0 = blockIdx.x * 16;
#pragma unroll
    for (int q = 0; q < 8; ++q) {
        int idx = q * 256 + t;
        int row = idx >> 7, c4 = idx & 127;
        *(float4*)(in_s + row * 512 + c4 * 4) =
            *(const float4*)(input + (size_t)(i0 + row) * 512 + c4 * 4);
    }
    __syncthreads();
    const int f = t & 63, rg = t >> 6;
    float acc[4] = {0.f, 0.f, 0.f, 0.f};
    const float* ip = in_s + rg * 4 * 512;
    for (int k = 0; k < 512; k += 4) {
        float w0 = __ldg(Wm + (k + 0) * 64 + f);
        float w1 = __ldg(Wm + (k + 1) * 64 + f);
        float w2 = __ldg(Wm + (k + 2) * 64 + f);
        float w3 = __ldg(Wm + (k + 3) * 64 + f);
#pragma unroll
        for (int i = 0; i < 4; ++i) {
            float4 iv = *(const float4*)(ip + i * 512 + k);
            acc[i] = fmaf(iv.x, w0, acc[i]);
            acc[i] = fmaf(iv.y, w1, acc[i]);
            acc[i] = fmaf(iv.z, w2, acc[i]);
            acc[i] = fmaf(iv.w, w3, acc[i]);
        }
    }
#pragma unroll
    for (int i = 0; i < 4; ++i)
        g_h[(size_t)(i0 + rg * 4 + i) * 64 + f] = acc[i];
}

// ---------------- kernel 1b/1c: scores + global max ----------------
__global__ __launch_bounds__(256) void k_scores(const float* __restrict__ av) {
    __shared__ float sdm[8];
    const int t = threadIdx.x, w = t >> 5, l = t & 31;
    const int row = blockIdx.x * 8 + w;
    float v0 = g_h[(size_t)row * 64 + l];
    float v1 = g_h[(size_t)row * 64 + 32 + l];
    float ss = v0 * __ldg(av + l) + v1 * __ldg(av + 32 + l);
    float sd = v0 * __ldg(av + 64 + l) + v1 * __ldg(av + 96 + l);
#pragma unroll
    for (int o = 16; o; o >>= 1) {
        ss += __shfl_xor_sync(0xffffffffu, ss, o);
        sd += __shfl_xor_sync(0xffffffffu, sd, o);
    }
    if (l == 0) { g_ssrc[row] = ss; g_sdst[row] = sd; sdm[w] = sd; }
    __syncthreads();
    if (t == 0) {
        float m = sdm[0];
#pragma unroll
        for (int i = 1; i < 8; ++i) m = fmaxf(m, sdm[i]);
        g_part[blockIdx.x] = m;
    }
}

__global__ __launch_bounds__(1024) void k_max() {
    __shared__ float s[1024];
    const int t = threadIdx.x;
    s[t] = g_part[t];
    __syncthreads();
    for (int o = 512; o; o >>= 1) {
        if (t < o) s[t] = fmaxf(s[t], s[t + o]);
        __syncthreads();
    }
    if (t == 0) g_gmax = s[0];
}

// ---------------- kernel 1d: g_hT[f][j] = tf32(g_h[j][f]) ----------------
__global__ __launch_bounds__(256) void k_trans() {
    __shared__ float ts[64][65];
    const int t = threadIdx.x;
    const int j0 = blockIdx.x * 64;
#pragma unroll
    for (int q = 0; q < 4; ++q) {
        int idx = q * 256 + t;
        int jj = idx >> 4, f4 = idx & 15;
        float4 v = *(const float4*)(g_h + (size_t)(j0 + jj) * 64 + f4 * 4);
        ts[jj][f4 * 4 + 0] = v.x; ts[jj][f4 * 4 + 1] = v.y;
        ts[jj][f4 * 4 + 2] = v.z; ts[jj][f4 * 4 + 3] = v.w;
    }
    __syncthreads();
#pragma unroll
    for (int q = 0; q < 4; ++q) {
        int idx = q * 256 + t;
        int f = idx >> 4, jv = idx & 15;
        uint4 u;
        u.x = f2tf32(ts[jv * 4 + 0][f]);
        u.y = f2tf32(ts[jv * 4 + 1][f]);
        u.z = f2tf32(ts[jv * 4 + 2][f]);
        u.w = f2tf32(ts[jv * 4 + 3][f]);
        *(uint4*)(g_hT + (size_t)f * Nn + j0 + jv * 4) = u;
    }
}

// ---------------- kernel 2: mma.sync tf32 attention ----------------
// grid 512 = 64 i-tiles(M=128) x 8 j-splits(K=1024). 256 threads = 8 warps x 16 rows.
// Dyn smem layout (bytes): P[128][64]f32 @0 (32KB), H[64][64]f32 @32768 (16KB),
//   c_s float2[128] @49152, zrow float[128] @50176, sdL float[64] @50688. Tot 50944.
#define SM_P   0
#define SM_H   32768
#define SM_CS  49152
#define SM_ZR  50176
#define SM_SDL 50688
#define SM_TOT 50944

__global__ __launch_bounds__(256, 2) void k_attn(const int* __restrict__ adj) {
    extern __shared__ char smem[];
    float* p_s = (float*)(smem + SM_P);
    float* h_t = (float*)(smem + SM_H);
    float2* c_s = (float2*)(smem + SM_CS);
    float* zrow = (float*)(smem + SM_ZR);
    float* sdL = (float*)(smem + SM_SDL);

    const int t = threadIdx.x;
    const int wid = t >> 5, lane = t & 31;
    const int g = lane >> 2, tig = lane & 3;        // mma groupID / thread-in-group
    const int i_tile = blockIdx.x >> 3, jq = blockIdx.x & 7;
    const int i0 = i_tile * 128, jb = jq * JW;

    if (t < 128) {
        float ss = g_ssrc[i0 + t];
        float u = ss + g_gmax;
        float m = fmaxf(u, GAT_ALPHA * u);
        c_s[t] = make_float2(LOG2E * ss, -LOG2E * m);
        zrow[t] = 0.f;
    }
    __syncthreads();

    // producer role: row r = t>>1, half = t&1 covers 32 j per chunk
    const int r = t >> 1, half = t & 1;
    const float2 cc = c_s[r];
    const size_t adjrow = (size_t)(i0 + r) * Nn + jb + half * 32;

    // mma role: A rows ra, ra+8 ; thread-constant swizzle masks
    const int ra = wid * 16 + g;
    const int xa = ((ra & 3) << 3) | (((ra >> 2) & 1) << 2);     // same for ra+8
    const int xb = ((g & 3) << 3) | (((g >> 2) & 1) << 2);       // for f = nt*8+g

    float acc[8][4];
#pragma unroll
    for (int n = 0; n < 8; ++n)
#pragma unroll
        for (int k = 0; k < 4; ++k) acc[n][k] = 0.f;
    float zp = 0.f;

    int4 abuf[8];
#pragma unroll
    for (int k = 0; k < 8; ++k) abuf[k] = *(const int4*)(adj + adjrow + k * 4);

    for (int c = 0; c < NCH; ++c) {
        const int j0 = c * 64;
        __syncthreads();                 // prev mma phase done with p_s/h_t

        // ---- stage H tile (from g_hT, swizzled) + sdL ----
        if (t < 64) sdL[t] = LOG2E * g_sdst[jb + j0 + t];
#pragma unroll
        for (int q = 0; q < 4; ++q) {
            int idx = q * 256 + t;
            int f = idx >> 4, j4 = idx & 15;
            float4 v = *(const float4*)(g_hT + (size_t)f * Nn + jb + j0 + j4 * 4);
            *(float4*)(h_t + f * 64 + swz(j4 * 4, f)) = v;
        }
        __syncthreads();                 // sdL ready for producers

        // ---- P producer: row r, j-local half*32..+31 ----
#pragma unroll
        for (int k4 = 0; k4 < 8; ++k4) {
            int4 a = abuf[k4];
            float4 sd = *(const float4*)(sdL + half * 32 + k4 * 4);
            float4 pv;
            { float u = cc.x + sd.x;
              float e = exp2f(fmaxf(u + cc.y, fmaf(GAT_ALPHA, u, cc.y)));
              pv.x = (a.x > 0) ? e : 0.f; }
            { float u = cc.x + sd.y;
              float e = exp2f(fmaxf(u + cc.y, fmaf(GAT_ALPHA, u, cc.y)));
              pv.y = (a.y > 0) ? e : 0.f; }
            { float u = cc.x + sd.z;
              float e = exp2f(fmaxf(u + cc.y, fmaf(GAT_ALPHA, u, cc.y)));
              pv.z = (a.z > 0) ? e : 0.f; }
            { float u = cc.x + sd.w;
              float e = exp2f(fmaxf(u + cc.y, fmaf(GAT_ALPHA, u, cc.y)));
              pv.w = (a.w > 0) ? e : 0.f; }
            zp += (pv.x + pv.y) + (pv.z + pv.w);
            float4 pt;
            pt.x = __uint_as_float(f2tf32(pv.x));
            pt.y = __uint_as_float(f2tf32(pv.y));
            pt.z = __uint_as_float(f2tf32(pv.z));
            pt.w = __uint_as_float(f2tf32(pv.w));
            *(float4*)(p_s + r * 64 + swz(half * 32 + k4 * 4, r)) = pt;
        }

        // ---- prefetch next chunk's adj (retires during mma phase) ----
        if (c < NCH - 1) {
#pragma unroll
            for (int k = 0; k < 8; ++k)
                abuf[k] = *(const int4*)(adj + adjrow + (c + 1) * 64 + k * 4);
        }
        __syncthreads();                 // p_s / h_t ready

        // ---- mma phase: warp does 16 rows x 64 feats ----
        const float* pa = p_s + ra * 64;
        const float* pa8 = p_s + (ra + 8) * 64;
#pragma unroll
        for (int ks = 0; ks < 8; ++ks) {
            const int k0 = (ks * 8) ^ (xa & 24);
            const int klo = (tig) | (xa & 4);
            uint32_t a0 = __float_as_uint(pa[k0 + klo]);
            uint32_t a2 = __float_as_uint(pa[k0 + (klo ^ 4)]);
            uint32_t a1 = __float_as_uint(pa8[k0 + klo]);
            uint32_t a3 = __float_as_uint(pa8[k0 + (klo ^ 4)]);
            const int kb0 = (ks * 8) ^ (xb & 24);
            const int kblo = (tig) | (xb & 4);
#pragma unroll
            for (int nt = 0; nt < 8; ++nt) {
                const float* pb = h_t + (nt * 8 + g) * 64;
                uint32_t b0 = __float_as_uint(pb[kb0 + kblo]);
                uint32_t b1 = __float_as_uint(pb[kb0 + (kblo ^ 4)]);
                mma_tf32(acc[nt], a0, a1, a2, a3, b0, b1);
            }
        }
    }

    // ---- z reduce + epilogue ----
    atomicAdd(&zrow[r], zp);
    __syncthreads();

    float* ob = g_o8 + (size_t)jq * Nn * 64;
#pragma unroll
    for (int nt = 0; nt < 8; ++nt) {
        const int col = nt * 8 + tig * 2;
        *(float2*)(ob + (size_t)(i0 + ra) * 64 + col) =
            make_float2(acc[nt][0], acc[nt][1]);
        *(float2*)(ob + (size_t)(i0 + ra + 8) * 64 + col) =
            make_float2(acc[nt][2], acc[nt][3]);
    }
    if (half == 0) g_z8[jq * Nn + i0 + r] = zrow[r];
}

// ---------------- kernel 3: combine + normalize ----------------
__global__ __launch_bounds__(256) void k_norm(float* __restrict__ out) {
    const int idx = blockIdx.x * 256 + threadIdx.x;
    const int row = idx >> 4;
    const float4* o0 = (const float4*)g_o8;
    float4 o = make_float4(0.f, 0.f, 0.f, 0.f);
    float z = 0.f;
#pragma unroll
    for (int k = 0; k < NJQ; ++k) {
        float4 a = o0[(size_t)k * Nn * 16 + idx];
        o.x += a.x; o.y += a.y; o.z += a.z; o.w += a.w;
        z += g_z8[k * Nn + row];
    }
    float zi = 1.0f / z;
    o.x *= zi; o.y *= zi; o.z *= zi; o.w *= zi;
    ((float4*)out)[idx] = o;
}

// ---------------- launch ----------------
extern "C" void kernel_launch(void* const* d_in, const int* in_sizes, int n_in,
                              void* d_out, int out_size) {
    const float* input = (const float*)d_in[0];
    const int*   adj   = (const int*)d_in[1];
    const float* Wm    = (const float*)d_in[2];
    const float* av    = (const float*)d_in[3];
    float* out = (float*)d_out;

    cudaFuncSetAttribute(k_attn, cudaFuncAttributeMaxDynamicSharedMemorySize, SM_TOT);

    k_proj<<<Nn / 16, 256>>>(input, Wm);
    k_scores<<<Nn / 8, 256>>>(av);
    k_max<<<1, 1024>>>();
    k_trans<<<Nn / 64, 256>>>();
    k_attn<<<512, 256, SM_TOT>>>(adj);
    k_norm<<<512, 256>>>(out);
}

// round 7
// speedup vs baseline: 1.3840x; 1.0526x over previous
#include <cuda_runtime.h>
#include <cstdint>

#define Nn 8192
#define GAT_ALPHA 0.2f
#define LOG2E 1.4426950408889634f
#define NJQ 8
#define JW 1024
#define NCH 16

// ---------------- scratch ----------------
__device__ float g_h[Nn * 64];
__device__ float g_ssrc[Nn];
__device__ float g_sdst[Nn];
__device__ float g_part[1024];
__device__ float g_gmax;
__device__ float g_eA[Nn];             // 2^(L*(ssrc - m))
__device__ float g_eC[Nn];             // 2^(L*(0.2*ssrc - m))
__device__ float g_eB[Nn];             // 2^(L*sdst)
__device__ float g_eD[Nn];             // 2^(0.2*L*sdst)
__device__ float2 g_hB[128 * 2048];    // H fragments: [chunk][ks][nt][lane]
__device__ float g_o8[NJQ * Nn * 64];
__device__ float g_z8[NJQ * Nn];

// ---------------- helpers ----------------
__device__ __forceinline__ uint32_t f2tf32(float x) {
    uint32_t r;
    asm("cvt.rna.tf32.f32 %0, %1;" : "=r"(r) : "f"(x));
    return r;
}
__device__ __forceinline__ void mma_tf32(float* c, uint32_t a0, uint32_t a1,
                                         uint32_t a2, uint32_t a3,
                                         uint32_t b0, uint32_t b1) {
    asm volatile(
        "mma.sync.aligned.m16n8k8.row.col.f32.tf32.tf32.f32 "
        "{%0,%1,%2,%3}, {%4,%5,%6,%7}, {%8,%9}, {%0,%1,%2,%3};"
        : "+f"(c[0]), "+f"(c[1]), "+f"(c[2]), "+f"(c[3])
        : "r"(a0), "r"(a1), "r"(a2), "r"(a3), "r"(b0), "r"(b1));
}
// 5-bit bank swizzle for P tile (same as R6, verified)
__device__ __forceinline__ int swz(int k, int r) {
    return k ^ ((r & 3) << 3) ^ (((r >> 2) & 1) << 2);
}

// ---------------- kernel 1: h = input @ W (fp32 FFMA, precision anchor) ----------------
__global__ __launch_bounds__(256) void k_proj(const float* __restrict__ input,
                                              const float* __restrict__ Wm) {
    __shared__ float in_s[16 * 512];
    const int t = threadIdx.x;
    const int i0 = blockIdx.x * 16;
#pragma unroll
    for (int q = 0; q < 8; ++q) {
        int idx = q * 256 + t;
        int row = idx >> 7, c4 = idx & 127;
        *(float4*)(in_s + row * 512 + c4 * 4) =
            *(const float4*)(input + (size_t)(i0 + row) * 512 + c4 * 4);
    }
    __syncthreads();
    const int f = t & 63, rg = t >> 6;
    float acc[4] = {0.f, 0.f, 0.f, 0.f};
    const float* ip = in_s + rg * 4 * 512;
    for (int k = 0; k < 512; k += 4) {
        float w0 = __ldg(Wm + (k + 0) * 64 + f);
        float w1 = __ldg(Wm + (k + 1) * 64 + f);
        float w2 = __ldg(Wm + (k + 2) * 64 + f);
        float w3 = __ldg(Wm + (k + 3) * 64 + f);
#pragma unroll
        for (int i = 0; i < 4; ++i) {
            float4 iv = *(const float4*)(ip + i * 512 + k);
            acc[i] = fmaf(iv.x, w0, acc[i]);
            acc[i] = fmaf(iv.y, w1, acc[i]);
            acc[i] = fmaf(iv.z, w2, acc[i]);
            acc[i] = fmaf(iv.w, w3, acc[i]);
        }
    }
#pragma unroll
    for (int i = 0; i < 4; ++i)
        g_h[(size_t)(i0 + rg * 4 + i) * 64 + f] = acc[i];
}

// ---------------- kernel 1b/1c: scores + global max ----------------
__global__ __launch_bounds__(256) void k_scores(const float* __restrict__ av) {
    __shared__ float sdm[8];
    const int t = threadIdx.x, w = t >> 5, l = t & 31;
    const int row = blockIdx.x * 8 + w;
    float v0 = g_h[(size_t)row * 64 + l];
    float v1 = g_h[(size_t)row * 64 + 32 + l];
    float ss = v0 * __ldg(av + l) + v1 * __ldg(av + 32 + l);
    float sd = v0 * __ldg(av + 64 + l) + v1 * __ldg(av + 96 + l);
#pragma unroll
    for (int o = 16; o; o >>= 1) {
        ss += __shfl_xor_sync(0xffffffffu, ss, o);
        sd += __shfl_xor_sync(0xffffffffu, sd, o);
    }
    if (l == 0) { g_ssrc[row] = ss; g_sdst[row] = sd; sdm[w] = sd; }
    __syncthreads();
    if (t == 0) {
        float m = sdm[0];
#pragma unroll
        for (int i = 1; i < 8; ++i) m = fmaxf(m, sdm[i]);
        g_part[blockIdx.x] = m;
    }
}

__global__ __launch_bounds__(1024) void k_max() {
    __shared__ float s[1024];
    const int t = threadIdx.x;
    s[t] = g_part[t];
    __syncthreads();
    for (int o = 512; o; o >>= 1) {
        if (t < o) s[t] = fmaxf(s[t], s[t + o]);
        __syncthreads();
    }
    if (t == 0) g_gmax = s[0];
}

// ---------------- kernel 1d: build H fragments + separable-exp factors ----------------
// One block per 64-j chunk. hs row stride 72 (72 mod 32 = 8 -> conflict-free frag reads).
__global__ __launch_bounds__(256) void k_prep() {
    __shared__ float hs[64 * 72];
    const int t = threadIdx.x;
    const int j0 = blockIdx.x * 64;
#pragma unroll
    for (int q = 0; q < 4; ++q) {
        int idx = q * 256 + t;              // 1024 float4
        int j = idx >> 4, f4 = idx & 15;
        float4 v = *(const float4*)(g_h + (size_t)(j0 + j) * 64 + f4 * 4);
        *(float4*)(hs + j * 72 + f4 * 4) = v;
    }
    if (t < 64) {
        int j = j0 + t;
        float sd = g_sdst[j];
        g_eB[j] = exp2f(LOG2E * sd);
        g_eD[j] = exp2f(0.2f * LOG2E * sd);
        float ss = g_ssrc[j];
        float u = ss + g_gmax;
        float m = fmaxf(u, GAT_ALPHA * u);
        g_eA[j] = exp2f(LOG2E * (ss - m));
        g_eC[j] = exp2f(LOG2E * (0.2f * ss - m));
    }
    __syncthreads();
    const int lane = t & 31, g = lane >> 2, tig = lane & 3;
#pragma unroll
    for (int q = 0; q < 8; ++q) {
        int idx = q * 256 + t;              // 2048 fragments-elements
        int ks = idx >> 8, nt = (idx >> 5) & 7;
        int f = nt * 8 + g;
        float2 v;
        v.x = __uint_as_float(f2tf32(hs[(ks * 8 + tig) * 72 + f]));
        v.y = __uint_as_float(f2tf32(hs[(ks * 8 + tig + 4) * 72 + f]));
        g_hB[(size_t)blockIdx.x * 2048 + idx] = v;
    }
}

// ---------------- kernel 2: mma.sync tf32 attention ----------------
// grid 512 = 64 i-tiles(M=128) x 8 j-splits(K=1024). 256 threads = 8 warps.
#define SM_P   0         // P [128][64] f32, swizzled (32KB)
#define SM_BF  32768     // H fragments float2[2048] (16KB)
#define SM_BJ  49152     // eB per chunk [64]
#define SM_DJ  49408     // eD per chunk [64]
#define SM_ZR  49664     // zrow [128]
#define SM_TOT 50176

__global__ __launch_bounds__(256, 2) void k_attn(const int* __restrict__ adj) {
    extern __shared__ char smem[];
    float* p_s = (float*)(smem + SM_P);
    float2* sBf = (float2*)(smem + SM_BF);
    float* sBj = (float*)(smem + SM_BJ);
    float* sDj = (float*)(smem + SM_DJ);
    float* zrow = (float*)(smem + SM_ZR);

    const int t = threadIdx.x;
    const int wid = t >> 5, lane = t & 31;
    const int g = lane >> 2, tig = lane & 3;
    const int i_tile = blockIdx.x >> 3, jq = blockIdx.x & 7;
    const int i0 = i_tile * 128, jb = jq * JW;

    if (t < 128) zrow[t] = 0.f;

    // producer role: row r = t>>1, half = t&1 covers 32 j per chunk
    const int r = t >> 1, half = t & 1;
    const float rowA = g_eA[i0 + r];
    const float rowC = g_eC[i0 + r];
    const size_t adjrow = (size_t)(i0 + r) * Nn + jb + half * 32;

    // mma role constants
    const int ra = wid * 16 + g;
    const int xa = ((ra & 3) << 3) | (((ra >> 2) & 1) << 2);

    float acc[8][4];
#pragma unroll
    for (int n = 0; n < 8; ++n)
#pragma unroll
        for (int k = 0; k < 4; ++k) acc[n][k] = 0.f;
    float zp = 0.f;

    int4 abuf[8];
#pragma unroll
    for (int k = 0; k < 8; ++k) abuf[k] = *(const int4*)(adj + adjrow + k * 4);

    for (int c = 0; c < NCH; ++c) {
        const int j0 = c * 64;
        __syncthreads();                 // prev mma done with p_s/sBf

        // ---- stage H fragments (straight coalesced copy) + eB/eD slice ----
        {
            const float4* src = (const float4*)g_hB + (size_t)((jb + j0) >> 6) * 1024;
            float4* dst = (float4*)sBf;
#pragma unroll
            for (int q = 0; q < 4; ++q)
                dst[q * 256 + t] = src[q * 256 + t];
        }
        if (t < 64) {
            sBj[t] = g_eB[jb + j0 + t];
            sDj[t] = g_eD[jb + j0 + t];
        }
        __syncthreads();

        // ---- P producer: p = mask ? max(A_i*B_j, C_i*D_j) : 0  (no MUFU) ----
#pragma unroll
        for (int k4 = 0; k4 < 8; ++k4) {
            int4 a = abuf[k4];
            float4 Bv = *(const float4*)(sBj + half * 32 + k4 * 4);
            float4 Dv = *(const float4*)(sDj + half * 32 + k4 * 4);
            float4 pv;
            pv.x = (a.x > 0) ? fmaxf(rowA * Bv.x, rowC * Dv.x) : 0.f;
            pv.y = (a.y > 0) ? fmaxf(rowA * Bv.y, rowC * Dv.y) : 0.f;
            pv.z = (a.z > 0) ? fmaxf(rowA * Bv.z, rowC * Dv.z) : 0.f;
            pv.w = (a.w > 0) ? fmaxf(rowA * Bv.w, rowC * Dv.w) : 0.f;
            zp += (pv.x + pv.y) + (pv.z + pv.w);
            float4 pt;
            pt.x = __uint_as_float(f2tf32(pv.x));
            pt.y = __uint_as_float(f2tf32(pv.y));
            pt.z = __uint_as_float(f2tf32(pv.z));
            pt.w = __uint_as_float(f2tf32(pv.w));
            *(float4*)(p_s + r * 64 + swz(half * 32 + k4 * 4, r)) = pt;
        }

        // ---- prefetch next chunk's adj (retires during mma) ----
        if (c < NCH - 1) {
#pragma unroll
            for (int k = 0; k < 8; ++k)
                abuf[k] = *(const int4*)(adj + adjrow + (c + 1) * 64 + k * 4);
        }
        __syncthreads();                 // p_s / sBf ready

        // ---- mma: warp covers 16 rows x 64 feats; B frags via LDS.64 ----
        const float* pa = p_s + ra * 64;
        const float* pa8 = p_s + (ra + 8) * 64;
#pragma unroll
        for (int ks = 0; ks < 8; ++ks) {
            const int k0 = (ks * 8) ^ (xa & 24);
            const int klo = tig | (xa & 4);
            uint32_t a0 = __float_as_uint(pa[k0 + klo]);
            uint32_t a2 = __float_as_uint(pa[k0 + (klo ^ 4)]);
            uint32_t a1 = __float_as_uint(pa8[k0 + klo]);
            uint32_t a3 = __float_as_uint(pa8[k0 + (klo ^ 4)]);
            const float2* bb = sBf + ks * 256 + lane;
#pragma unroll
            for (int nt = 0; nt < 8; ++nt) {
                float2 b = bb[nt * 32];
                mma_tf32(acc[nt], a0, a1, a2, a3,
                         __float_as_uint(b.x), __float_as_uint(b.y));
            }
        }
    }

    // ---- z reduce + epilogue ----
    atomicAdd(&zrow[r], zp);
    __syncthreads();

    float* ob = g_o8 + (size_t)jq * Nn * 64;
#pragma unroll
    for (int nt = 0; nt < 8; ++nt) {
        const int col = nt * 8 + tig * 2;
        *(float2*)(ob + (size_t)(i0 + ra) * 64 + col) =
            make_float2(acc[nt][0], acc[nt][1]);
        *(float2*)(ob + (size_t)(i0 + ra + 8) * 64 + col) =
            make_float2(acc[nt][2], acc[nt][3]);
    }
    if (half == 0) g_z8[jq * Nn + i0 + r] = zrow[r];
}

// ---------------- kernel 3: combine + normalize ----------------
__global__ __launch_bounds__(256) void k_norm(float* __restrict__ out) {
    const int idx = blockIdx.x * 256 + threadIdx.x;
    const int row = idx >> 4;
    const float4* o0 = (const float4*)g_o8;
    float4 o = make_float4(0.f, 0.f, 0.f, 0.f);
    float z = 0.f;
#pragma unroll
    for (int k = 0; k < NJQ; ++k) {
        float4 a = o0[(size_t)k * Nn * 16 + idx];
        o.x += a.x; o.y += a.y; o.z += a.z; o.w += a.w;
        z += g_z8[k * Nn + row];
    }
    float zi = 1.0f / z;
    o.x *= zi; o.y *= zi; o.z *= zi; o.w *= zi;
    ((float4*)out)[idx] = o;
}

// ---------------- launch ----------------
extern "C" void kernel_launch(void* const* d_in, const int* in_sizes, int n_in,
                              void* d_out, int out_size) {
    const float* input = (const float*)d_in[0];
    const int*   adj   = (const int*)d_in[1];
    const float* Wm    = (const float*)d_in[2];
    const float* av    = (const float*)d_in[3];
    float* out = (float*)d_out;

    cudaFuncSetAttribute(k_attn, cudaFuncAttributeMaxDynamicSharedMemorySize, SM_TOT);

    k_proj<<<Nn / 16, 256>>>(input, Wm);
    k_scores<<<Nn / 8, 256>>>(av);
    k_max<<<1, 1024>>>();
    k_prep<<<Nn / 64, 256>>>();
    k_attn<<<512, 256, SM_TOT>>>(adj);
    k_norm<<<512, 256>>>(out);
}

// round 8
// speedup vs baseline: 1.5619x; 1.1286x over previous
#include <cuda_runtime.h>
#include <cstdint>

#define Nn 8192
#define GAT_ALPHA 0.2f
#define LOG2E 1.4426950408889634f
#define NJQ 8
#define JW 1024
#define NCH 16

// ---------------- scratch ----------------
__device__ float g_h[Nn * 64];
__device__ float g_ssrc[Nn];
__device__ float g_sdst[Nn];
__device__ float g_part[1024];
__device__ float g_gmax;
__device__ float g_eA[Nn];                 // 2^(L*(ssrc - m))
__device__ float g_eC[Nn];                 // 2^(L*(0.2*ssrc - m))
__device__ float2 g_eBD[Nn];               // {2^(L*sdst), 2^(0.2*L*sdst)}
__device__ float2 g_hB[128 * 2048];        // H fragments: [chunk][ks][nt][lane]
__device__ unsigned g_adjb[Nn * (Nn / 32)];// bit-packed adj, row-major words
__device__ float g_o8[NJQ * Nn * 64];
__device__ float g_z8[NJQ * Nn];

// ---------------- helpers ----------------
__device__ __forceinline__ uint32_t f2tf32(float x) {
    uint32_t r;
    asm("cvt.rna.tf32.f32 %0, %1;" : "=r"(r) : "f"(x));
    return r;
}
__device__ __forceinline__ void mma_tf32(float* c, uint32_t a0, uint32_t a1,
                                         uint32_t a2, uint32_t a3,
                                         uint32_t b0, uint32_t b1) {
    asm volatile(
        "mma.sync.aligned.m16n8k8.row.col.f32.tf32.tf32.f32 "
        "{%0,%1,%2,%3}, {%4,%5,%6,%7}, {%8,%9}, {%0,%1,%2,%3};"
        : "+f"(c[0]), "+f"(c[1]), "+f"(c[2]), "+f"(c[3])
        : "r"(a0), "r"(a1), "r"(a2), "r"(a3), "r"(b0), "r"(b1));
}
__device__ __forceinline__ uint32_t smem_u32(const void* p) {
    uint32_t a;
    asm("{ .reg .u64 t; cvta.to.shared.u64 t, %1; cvt.u32.u64 %0, t; }"
        : "=r"(a) : "l"(p));
    return a;
}
__device__ __forceinline__ void cp_async16(uint32_t s, const void* g) {
    asm volatile("{\n\t.reg .u64 ga;\n\tcvta.to.global.u64 ga, %1;\n\t"
                 "cp.async.cg.shared.global [%0], [ga], 16;\n\t}"
                 :: "r"(s), "l"(g) : "memory");
}
#define CP_COMMIT() asm volatile("cp.async.commit_group;" ::: "memory")
#define CP_WAIT1()  asm volatile("cp.async.wait_group 1;" ::: "memory")

// ---------------- kernel 0: bit-pack adj ----------------
__global__ __launch_bounds__(256) void k_pack(const int* __restrict__ adj) {
    const size_t stride = (size_t)gridDim.x * 256;
    size_t idx = (size_t)blockIdx.x * 256 + threadIdx.x;
    const size_t total = (size_t)Nn * Nn;
    for (; idx < total; idx += stride) {
        int a = adj[idx];
        unsigned b = __ballot_sync(0xffffffffu, a > 0);
        if ((threadIdx.x & 31) == 0) g_adjb[idx >> 5] = b;
    }
}

// ---------------- kernel 1: h = input @ W (fp32, precision anchor) ----------------
__global__ __launch_bounds__(256) void k_proj(const float* __restrict__ input,
                                              const float* __restrict__ Wm) {
    __shared__ float in_s[16 * 512];
    const int t = threadIdx.x;
    const int i0 = blockIdx.x * 16;
#pragma unroll
    for (int q = 0; q < 8; ++q) {
        int idx = q * 256 + t;
        int row = idx >> 7, c4 = idx & 127;
        *(float4*)(in_s + row * 512 + c4 * 4) =
            *(const float4*)(input + (size_t)(i0 + row) * 512 + c4 * 4);
    }
    __syncthreads();
    const int f = t & 63, rg = t >> 6;
    float acc[4] = {0.f, 0.f, 0.f, 0.f};
    const float* ip = in_s + rg * 4 * 512;
    for (int k = 0; k < 512; k += 4) {
        float w0 = __ldg(Wm + (k + 0) * 64 + f);
        float w1 = __ldg(Wm + (k + 1) * 64 + f);
        float w2 = __ldg(Wm + (k + 2) * 64 + f);
        float w3 = __ldg(Wm + (k + 3) * 64 + f);
#pragma unroll
        for (int i = 0; i < 4; ++i) {
            float4 iv = *(const float4*)(ip + i * 512 + k);
            acc[i] = fmaf(iv.x, w0, acc[i]);
            acc[i] = fmaf(iv.y, w1, acc[i]);
            acc[i] = fmaf(iv.z, w2, acc[i]);
            acc[i] = fmaf(iv.w, w3, acc[i]);
        }
    }
#pragma unroll
    for (int i = 0; i < 4; ++i)
        g_h[(size_t)(i0 + rg * 4 + i) * 64 + f] = acc[i];
}

// ---------------- kernel 1b/1c: scores + global max ----------------
__global__ __launch_bounds__(256) void k_scores(const float* __restrict__ av) {
    __shared__ float sdm[8];
    const int t = threadIdx.x, w = t >> 5, l = t & 31;
    const int row = blockIdx.x * 8 + w;
    float v0 = g_h[(size_t)row * 64 + l];
    float v1 = g_h[(size_t)row * 64 + 32 + l];
    float ss = v0 * __ldg(av + l) + v1 * __ldg(av + 32 + l);
    float sd = v0 * __ldg(av + 64 + l) + v1 * __ldg(av + 96 + l);
#pragma unroll
    for (int o = 16; o; o >>= 1) {
        ss += __shfl_xor_sync(0xffffffffu, ss, o);
        sd += __shfl_xor_sync(0xffffffffu, sd, o);
    }
    if (l == 0) { g_ssrc[row] = ss; g_sdst[row] = sd; sdm[w] = sd; }
    __syncthreads();
    if (t == 0) {
        float m = sdm[0];
#pragma unroll
        for (int i = 1; i < 8; ++i) m = fmaxf(m, sdm[i]);
        g_part[blockIdx.x] = m;
    }
}

__global__ __launch_bounds__(1024) void k_max() {
    __shared__ float s[1024];
    const int t = threadIdx.x;
    s[t] = g_part[t];
    __syncthreads();
    for (int o = 512; o; o >>= 1) {
        if (t < o) s[t] = fmaxf(s[t], s[t + o]);
        __syncthreads();
    }
    if (t == 0) g_gmax = s[0];
}

// ---------------- kernel 1d: H fragments + separable-exp factors ----------------
__global__ __launch_bounds__(256) void k_prep() {
    __shared__ float hs[64 * 72];
    const int t = threadIdx.x;
    const int j0 = blockIdx.x * 64;
#pragma unroll
    for (int q = 0; q < 4; ++q) {
        int idx = q * 256 + t;
        int j = idx >> 4, f4 = idx & 15;
        float4 v = *(const float4*)(g_h + (size_t)(j0 + j) * 64 + f4 * 4);
        *(float4*)(hs + j * 72 + f4 * 4) = v;
    }
    if (t < 64) {
        int j = j0 + t;
        float sd = g_sdst[j];
        g_eBD[j] = make_float2(exp2f(LOG2E * sd), exp2f(0.2f * LOG2E * sd));
        float ss = g_ssrc[j];
        float u = ss + g_gmax;
        float m = fmaxf(u, GAT_ALPHA * u);
        g_eA[j] = exp2f(LOG2E * (ss - m));
        g_eC[j] = exp2f(LOG2E * (0.2f * ss - m));
    }
    __syncthreads();
    const int lane = t & 31, g = lane >> 2, tig = lane & 3;
#pragma unroll
    for (int q = 0; q < 8; ++q) {
        int idx = q * 256 + t;
        int ks = idx >> 8, nt = (idx >> 5) & 7;
        int f = nt * 8 + g;
        float2 v;
        v.x = __uint_as_float(f2tf32(hs[(ks * 8 + tig) * 72 + f]));
        v.y = __uint_as_float(f2tf32(hs[(ks * 8 + tig + 4) * 72 + f]));
        g_hB[(size_t)blockIdx.x * 2048 + idx] = v;
    }
}

// ---------------- kernel 2: fused register-P mma attention ----------------
// grid 512 = 64 i-tiles(M=128) x 8 j-splits. 256 thr = 8 warps, warp rows {ra, ra+8}.
// SMEM: H frags 2x16KB double-buffered (cp.async) + eBD 2x512B. No P tile.
#define SM_H   0
#define SM_BD  32768
#define SM_TOT 33792

__global__ __launch_bounds__(256, 3) void k_attn() {
    extern __shared__ char smem[];
    const uint32_t sb = smem_u32(smem);

    const int t = threadIdx.x;
    const int wid = t >> 5, lane = t & 31;
    const int g = lane >> 2, tig = lane & 3;
    const int i_tile = blockIdx.x >> 3, jq = blockIdx.x & 7;
    const int i0 = i_tile * 128, jb = jq * JW;

    const int ra = wid * 16 + g;
    const float eA0 = g_eA[i0 + ra],     eC0 = g_eC[i0 + ra];
    const float eA1 = g_eA[i0 + ra + 8], eC1 = g_eC[i0 + ra + 8];

    const unsigned* bw0 = g_adjb + (size_t)(i0 + ra) * (Nn / 32) + (jb >> 5);
    const unsigned* bw1 = g_adjb + (size_t)(i0 + ra + 8) * (Nn / 32) + (jb >> 5);

    float acc[8][4];
#pragma unroll
    for (int n = 0; n < 8; ++n)
#pragma unroll
        for (int k = 0; k < 4; ++k) acc[n][k] = 0.f;
    float zp0 = 0.f, zp1 = 0.f;

    // ---- stage helper (16KB H + 512B eBD per chunk) ----
    auto stage = [&](int c, int buf) {
        const float4* src = (const float4*)g_hB + (size_t)((jb + c * 64) >> 6) * 1024;
        uint32_t dst = sb + SM_H + buf * 16384;
#pragma unroll
        for (int q = 0; q < 4; ++q)
            cp_async16(dst + (q * 256 + t) * 16, src + q * 256 + t);
        if (t < 32)
            cp_async16(sb + SM_BD + buf * 512 + t * 16,
                       (const char*)(g_eBD + jb + c * 64) + t * 16);
    };

    // prologue: stage chunks 0,1; prefetch adj bits for chunk 0
    stage(0, 0); CP_COMMIT();
    stage(1, 1); CP_COMMIT();
    uint2 ab0 = *(const uint2*)(bw0);
    uint2 ab1 = *(const uint2*)(bw1);

    for (int c = 0; c < NCH; ++c) {
        const int buf = c & 1;
        CP_WAIT1();
        __syncthreads();                     // staged data visible; prev issue safe

        const float2* sBf = (const float2*)(smem + SM_H + buf * 16384);
        const float2* sBD = (const float2*)(smem + SM_BD + buf * 512);

        const uint2 cb0 = ab0, cb1 = ab1;
        if (c + 1 < NCH) {                   // prefetch next chunk's bits
            ab0 = *(const uint2*)(bw0 + (c + 1) * 2);
            ab1 = *(const uint2*)(bw1 + (c + 1) * 2);
        }

#pragma unroll
        for (int ks = 0; ks < 8; ++ks) {
            const int jl0 = ks * 8 + tig, jl1 = jl0 + 4;
            const unsigned w0 = (ks < 4) ? cb0.x : cb0.y;
            const unsigned w1 = (ks < 4) ? cb1.x : cb1.y;
            const int sh0 = jl0 & 31, sh1 = jl1 & 31;
            float2 bd0 = sBD[jl0];
            float2 bd1 = sBD[jl1];
            float v00 = fmaxf(eA0 * bd0.x, eC0 * bd0.y);   // row ra,   j0
            float v01 = fmaxf(eA0 * bd1.x, eC0 * bd1.y);   // row ra,   j1
            float v10 = fmaxf(eA1 * bd0.x, eC1 * bd0.y);   // row ra+8, j0
            float v11 = fmaxf(eA1 * bd1.x, eC1 * bd1.y);   // row ra+8, j1
            float p00 = ((w0 >> sh0) & 1u) ? v00 : 0.f;
            float p01 = ((w0 >> sh1) & 1u) ? v01 : 0.f;
            float p10 = ((w1 >> sh0) & 1u) ? v10 : 0.f;
            float p11 = ((w1 >> sh1) & 1u) ? v11 : 0.f;
            zp0 += p00 + p01;
            zp1 += p10 + p11;
            uint32_t a0 = f2tf32(p00), a1 = f2tf32(p10);
            uint32_t a2 = f2tf32(p01), a3 = f2tf32(p11);
            const float2* bb = sBf + ks * 256 + lane;
#pragma unroll
            for (int nt = 0; nt < 8; ++nt) {
                float2 b = bb[nt * 32];
                mma_tf32(acc[nt], a0, a1, a2, a3,
                         __float_as_uint(b.x), __float_as_uint(b.y));
            }
        }
        __syncthreads();                     // all warps done reading buf
        if (c + 2 < NCH) { stage(c + 2, buf); CP_COMMIT(); }
        else             { CP_COMMIT(); }    // empty group keeps wait_group aligned
    }

    // ---- z quad-reduce (lanes g*4+tig) + epilogue ----
    zp0 += __shfl_xor_sync(0xffffffffu, zp0, 1);
    zp0 += __shfl_xor_sync(0xffffffffu, zp0, 2);
    zp1 += __shfl_xor_sync(0xffffffffu, zp1, 1);
    zp1 += __shfl_xor_sync(0xffffffffu, zp1, 2);
    if (tig == 0) {
        g_z8[jq * Nn + i0 + ra] = zp0;
        g_z8[jq * Nn + i0 + ra + 8] = zp1;
    }

    float* ob = g_o8 + (size_t)jq * Nn * 64;
#pragma unroll
    for (int nt = 0; nt < 8; ++nt) {
        const int col = nt * 8 + tig * 2;
        *(float2*)(ob + (size_t)(i0 + ra) * 64 + col) =
            make_float2(acc[nt][0], acc[nt][1]);
        *(float2*)(ob + (size_t)(i0 + ra + 8) * 64 + col) =
            make_float2(acc[nt][2], acc[nt][3]);
    }
}

// ---------------- kernel 3: combine + normalize ----------------
__global__ __launch_bounds__(256) void k_norm(float* __restrict__ out) {
    const int idx = blockIdx.x * 256 + threadIdx.x;
    const int row = idx >> 4;
    const float4* o0 = (const float4*)g_o8;
    float4 o = make_float4(0.f, 0.f, 0.f, 0.f);
    float z = 0.f;
#pragma unroll
    for (int k = 0; k < NJQ; ++k) {
        float4 a = o0[(size_t)k * Nn * 16 + idx];
        o.x += a.x; o.y += a.y; o.z += a.z; o.w += a.w;
        z += g_z8[k * Nn + row];
    }
    float zi = 1.0f / z;
    o.x *= zi; o.y *= zi; o.z *= zi; o.w *= zi;
    ((float4*)out)[idx] = o;
}

// ---------------- launch ----------------
extern "C" void kernel_launch(void* const* d_in, const int* in_sizes, int n_in,
                              void* d_out, int out_size) {
    const float* input = (const float*)d_in[0];
    const int*   adj   = (const int*)d_in[1];
    const float* Wm    = (const float*)d_in[2];
    const float* av    = (const float*)d_in[3];
    float* out = (float*)d_out;

    cudaFuncSetAttribute(k_attn, cudaFuncAttributeMaxDynamicSharedMemorySize, SM_TOT);

    k_pack<<<2048, 256>>>(adj);
    k_proj<<<Nn / 16, 256>>>(input, Wm);
    k_scores<<<Nn / 8, 256>>>(av);
    k_max<<<1, 1024>>>();
    k_prep<<<Nn / 64, 256>>>();
    k_attn<<<512, 256, SM_TOT>>>();
    k_norm<<<512, 256>>>(out);
}

// round 10
// speedup vs baseline: 2.4654x; 1.5785x over previous
#include <cuda_runtime.h>
#include <cuda_fp16.h>
#include <cstdint>

#define Nn 8192
#define GAT_ALPHA 0.2f
#define LOG2E 1.4426950408889634f
#define NJQ 8
#define JW 1024
#define NCH 16

// ---------------- scratch ----------------
__device__ float g_h[Nn * 64];
__device__ float g_ssrc[Nn];
__device__ float g_sdst[Nn];
__device__ unsigned g_gmax_u;
__device__ float g_eA[Nn];                 // 2^(L*(ssrc - m))
__device__ float g_eC[Nn];                 // 2^(L*(0.2*ssrc - m))
__device__ float2 g_eBD[Nn];               // {2^(L*sdst), 2^(0.2*L*sdst)}
__device__ uint2 g_hBh[128 * 1024];        // fp16 B frags: [chunk][ks4][nt8][lane32]
__device__ unsigned g_adjb[Nn * (Nn / 32)];
__device__ float g_o8[NJQ * Nn * 64];
__device__ float g_z8[NJQ * Nn];

// ---------------- helpers ----------------
__device__ __forceinline__ uint32_t h2pack(float hi, float lo) {
    uint32_t r;
    asm("cvt.rn.f16x2.f32 %0, %1, %2;" : "=r"(r) : "f"(hi), "f"(lo));
    return r;
}
__device__ __forceinline__ float2 h2unpack(uint32_t v) {
    __half2 h = *reinterpret_cast<__half2*>(&v);
    return __half22float2(h);
}
__device__ __forceinline__ void mma_f16(float* c, uint32_t a0, uint32_t a1,
                                        uint32_t a2, uint32_t a3,
                                        uint32_t b0, uint32_t b1) {
    asm volatile(
        "mma.sync.aligned.m16n8k16.row.col.f32.f16.f16.f32 "
        "{%0,%1,%2,%3}, {%4,%5,%6,%7}, {%8,%9}, {%0,%1,%2,%3};"
        : "+f"(c[0]), "+f"(c[1]), "+f"(c[2]), "+f"(c[3])
        : "r"(a0), "r"(a1), "r"(a2), "r"(a3), "r"(b0), "r"(b1));
}
__device__ __forceinline__ uint32_t smem_u32(const void* p) {
    uint32_t a;
    asm("{ .reg .u64 t; cvta.to.shared.u64 t, %1; cvt.u32.u64 %0, t; }"
        : "=r"(a) : "l"(p));
    return a;
}
__device__ __forceinline__ void cp_async16(uint32_t s, const void* g) {
    asm volatile("{\n\t.reg .u64 ga;\n\tcvta.to.global.u64 ga, %1;\n\t"
                 "cp.async.cg.shared.global [%0], [ga], 16;\n\t}"
                 :: "r"(s), "l"(g) : "memory");
}
#define CP_COMMIT() asm volatile("cp.async.commit_group;" ::: "memory")
#define CP_WAIT1()  asm volatile("cp.async.wait_group 1;" ::: "memory")

__device__ __forceinline__ unsigned fenc(float f) {     // order-preserving
    unsigned b = __float_as_uint(f);
    return (b & 0x80000000u) ? ~b : (b | 0x80000000u);
}
__device__ __forceinline__ float fdec(unsigned u) {
    unsigned b = (u & 0x80000000u) ? (u & 0x7FFFFFFFu) : ~u;
    return __uint_as_float(b);
}

// ---------------- kernel 1: fused [proj | pack] via block specialization ----------------
// blocks [0,512): h = input @ W (16 rows each). blocks [512,2560): bit-pack adj.
__global__ __launch_bounds__(256) void k_packproj(const float* __restrict__ input,
                                                  const float* __restrict__ Wm,
                                                  const int* __restrict__ adj) {
    __shared__ float in_s[16 * 512];
    const int t = threadIdx.x;
    if (blockIdx.x < 512) {
        const int i0 = blockIdx.x * 16;
#pragma unroll
        for (int q = 0; q < 8; ++q) {
            int idx = q * 256 + t;
            int row = idx >> 7, c4 = idx & 127;
            *(float4*)(in_s + row * 512 + c4 * 4) =
                *(const float4*)(input + (size_t)(i0 + row) * 512 + c4 * 4);
        }
        __syncthreads();
        const int f = t & 63, rg = t >> 6;
        float acc[4] = {0.f, 0.f, 0.f, 0.f};
        const float* ip = in_s + rg * 4 * 512;
        for (int k = 0; k < 512; k += 4) {
            float w0 = __ldg(Wm + (k + 0) * 64 + f);
            float w1 = __ldg(Wm + (k + 1) * 64 + f);
            float w2 = __ldg(Wm + (k + 2) * 64 + f);
            float w3 = __ldg(Wm + (k + 3) * 64 + f);
#pragma unroll
            for (int i = 0; i < 4; ++i) {
                float4 iv = *(const float4*)(ip + i * 512 + k);
                acc[i] = fmaf(iv.x, w0, acc[i]);
                acc[i] = fmaf(iv.y, w1, acc[i]);
                acc[i] = fmaf(iv.z, w2, acc[i]);
                acc[i] = fmaf(iv.w, w3, acc[i]);
            }
        }
#pragma unroll
        for (int i = 0; i < 4; ++i)
            g_h[(size_t)(i0 + rg * 4 + i) * 64 + f] = acc[i];
    } else {
        if (blockIdx.x == 512 && t == 0) g_gmax_u = 0u;   // reset per launch
        const int l = t & 31;
        const size_t tid4 = (size_t)(blockIdx.x - 512) * 256 + t;
        const int4* adj4 = (const int4*)adj;
#pragma unroll 1
        for (int it = 0; it < 32; it += 4) {
            int4 v[4];
#pragma unroll
            for (int k = 0; k < 4; ++k)
                v[k] = adj4[tid4 + (size_t)(it + k) * 524288];
#pragma unroll
            for (int k = 0; k < 4; ++k) {
                unsigned n = (unsigned)(v[k].x > 0) | ((unsigned)(v[k].y > 0) << 1) |
                             ((unsigned)(v[k].z > 0) << 2) | ((unsigned)(v[k].w > 0) << 3);
                unsigned u = n << ((l & 7) * 4);
                u |= __shfl_xor_sync(0xffffffffu, u, 1);
                u |= __shfl_xor_sync(0xffffffffu, u, 2);
                u |= __shfl_xor_sync(0xffffffffu, u, 4);
                if ((l & 7) == 0)
                    g_adjb[(tid4 + (size_t)(it + k) * 524288) >> 3] = u;
            }
        }
    }
}

// ---------------- kernel 2: scores + fused global max ----------------
__global__ __launch_bounds__(256) void k_scores(const float* __restrict__ av) {
    __shared__ float sdm[8];
    const int t = threadIdx.x, w = t >> 5, l = t & 31;
    const int row = blockIdx.x * 8 + w;
    float v0 = g_h[(size_t)row * 64 + l];
    float v1 = g_h[(size_t)row * 64 + 32 + l];
    float ss = v0 * __ldg(av + l) + v1 * __ldg(av + 32 + l);
    float sd = v0 * __ldg(av + 64 + l) + v1 * __ldg(av + 96 + l);
#pragma unroll
    for (int o = 16; o; o >>= 1) {
        ss += __shfl_xor_sync(0xffffffffu, ss, o);
        sd += __shfl_xor_sync(0xffffffffu, sd, o);
    }
    if (l == 0) { g_ssrc[row] = ss; g_sdst[row] = sd; sdm[w] = sd; }
    __syncthreads();
    if (t == 0) {
        float m = sdm[0];
#pragma unroll
        for (int i = 1; i < 8; ++i) m = fmaxf(m, sdm[i]);
        atomicMax(&g_gmax_u, fenc(m));
    }
}

// ---------------- kernel 3: fp16 B fragments + separable-exp factors ----------------
__global__ __launch_bounds__(256) void k_prep() {
    __shared__ float hs[64 * 72];
    const int t = threadIdx.x;
    const int j0 = blockIdx.x * 64;
    const float gmax = fdec(g_gmax_u);
#pragma unroll
    for (int q = 0; q < 4; ++q) {
        int idx = q * 256 + t;
        int j = idx >> 4, f4 = idx & 15;
        float4 v = *(const float4*)(g_h + (size_t)(j0 + j) * 64 + f4 * 4);
        *(float4*)(hs + j * 72 + f4 * 4) = v;
    }
    if (t < 64) {
        int j = j0 + t;
        float sd = g_sdst[j];
        g_eBD[j] = make_float2(exp2f(LOG2E * sd), exp2f(0.2f * LOG2E * sd));
        float ss = g_ssrc[j];
        float u = ss + gmax;
        float m = fmaxf(u, GAT_ALPHA * u);
        g_eA[j] = exp2f(LOG2E * (ss - m));
        g_eC[j] = exp2f(LOG2E * (0.2f * ss - m));
    }
    __syncthreads();
#pragma unroll
    for (int q = 0; q < 4; ++q) {
        int idx = q * 256 + t;                 // [ks4][nt8][lane32]
        int ks = idx >> 8, nt = (idx >> 5) & 7, lane = idx & 31;
        int g = lane >> 2, tig = lane & 3;
        int f = nt * 8 + g, jl = ks * 16 + 2 * tig;
        uint2 b;
        b.x = h2pack(hs[(jl + 1) * 72 + f], hs[jl * 72 + f]);
        b.y = h2pack(hs[(jl + 9) * 72 + f], hs[(jl + 8) * 72 + f]);
        g_hBh[(size_t)blockIdx.x * 1024 + idx] = b;
    }
}

// ---------------- kernel 4: fused register-P fp16 mma attention ----------------
// grid 512 = 64 i-tiles(M=128) x 8 j-splits. 256 thr = 8 warps, rows {ra, ra+8}.
#define SM_H   0         // fp16 B frags, 2 x 8KB double-buffered
#define SM_BD  16384     // eBD, 2 x 512B
#define SM_TOT 17408

__global__ __launch_bounds__(256, 3) void k_attn() {
    extern __shared__ char smem[];
    const uint32_t sb = smem_u32(smem);

    const int t = threadIdx.x;
    const int wid = t >> 5, lane = t & 31;
    const int g = lane >> 2, tig = lane & 3;
    const int i_tile = blockIdx.x >> 3, jq = blockIdx.x & 7;
    const int i0 = i_tile * 128, jb = jq * JW;

    const int ra = wid * 16 + g;
    const float eA0 = g_eA[i0 + ra],     eC0 = g_eC[i0 + ra];
    const float eA1 = g_eA[i0 + ra + 8], eC1 = g_eC[i0 + ra + 8];

    const unsigned* bw0 = g_adjb + (size_t)(i0 + ra) * (Nn / 32) + (jb >> 5);
    const unsigned* bw1 = g_adjb + (size_t)(i0 + ra + 8) * (Nn / 32) + (jb >> 5);

    float acc[8][4];
#pragma unroll
    for (int n = 0; n < 8; ++n)
#pragma unroll
        for (int k = 0; k < 4; ++k) acc[n][k] = 0.f;
    float zp0 = 0.f, zp1 = 0.f;

    auto stage = [&](int c, int buf) {
        const float4* src = (const float4*)g_hBh + (size_t)((jb + c * 64) >> 6) * 512;
        uint32_t dst = sb + SM_H + buf * 8192;
#pragma unroll
        for (int q = 0; q < 2; ++q)
            cp_async16(dst + (q * 256 + t) * 16, src + q * 256 + t);
        if (t < 32)
            cp_async16(sb + SM_BD + buf * 512 + t * 16,
                       (const char*)(g_eBD + jb + c * 64) + t * 16);
    };

    stage(0, 0); CP_COMMIT();
    stage(1, 1); CP_COMMIT();
    uint2 ab0 = *(const uint2*)(bw0);
    uint2 ab1 = *(const uint2*)(bw1);

    for (int c = 0; c < NCH; ++c) {
        const int buf = c & 1;
        CP_WAIT1();
        __syncthreads();

        const uint2* sBf = (const uint2*)(smem + SM_H + buf * 8192);
        const float2* sBD = (const float2*)(smem + SM_BD + buf * 512);

        const uint2 cb0 = ab0, cb1 = ab1;
        if (c + 1 < NCH) {
            ab0 = *(const uint2*)(bw0 + (c + 1) * 2);
            ab1 = *(const uint2*)(bw1 + (c + 1) * 2);
        }

#pragma unroll
        for (int ks = 0; ks < 4; ++ks) {
            const int jl = ks * 16 + 2 * tig;
            const int s = jl & 31;
            const unsigned w0 = (ks < 2) ? cb0.x : cb0.y;
            const unsigned w1 = (ks < 2) ? cb1.x : cb1.y;
            float2 bdA = sBD[jl],     bdB = sBD[jl + 1];
            float2 bdC = sBD[jl + 8], bdD = sBD[jl + 9];

            float p00 = ((w0 >> s) & 1u)       ? fmaxf(eA0 * bdA.x, eC0 * bdA.y) : 0.f;
            float p01 = ((w0 >> (s + 1)) & 1u) ? fmaxf(eA0 * bdB.x, eC0 * bdB.y) : 0.f;
            float p08 = ((w0 >> (s + 8)) & 1u) ? fmaxf(eA0 * bdC.x, eC0 * bdC.y) : 0.f;
            float p09 = ((w0 >> (s + 9)) & 1u) ? fmaxf(eA0 * bdD.x, eC0 * bdD.y) : 0.f;
            float p10 = ((w1 >> s) & 1u)       ? fmaxf(eA1 * bdA.x, eC1 * bdA.y) : 0.f;
            float p11 = ((w1 >> (s + 1)) & 1u) ? fmaxf(eA1 * bdB.x, eC1 * bdB.y) : 0.f;
            float p18 = ((w1 >> (s + 8)) & 1u) ? fmaxf(eA1 * bdC.x, eC1 * bdC.y) : 0.f;
            float p19 = ((w1 >> (s + 9)) & 1u) ? fmaxf(eA1 * bdD.x, eC1 * bdD.y) : 0.f;

            uint32_t a0 = h2pack(p01, p00);
            uint32_t a1 = h2pack(p11, p10);
            uint32_t a2 = h2pack(p09, p08);
            uint32_t a3 = h2pack(p19, p18);

            // z accumulated from the EXACT fp16 values fed to the MMA
            float2 f0 = h2unpack(a0), f2 = h2unpack(a2);
            float2 f1 = h2unpack(a1), f3 = h2unpack(a3);
            zp0 += (f0.x + f0.y) + (f2.x + f2.y);
            zp1 += (f1.x + f1.y) + (f3.x + f3.y);

            const uint2* bb = sBf + ks * 256 + lane;
#pragma unroll
            for (int nt = 0; nt < 8; ++nt) {
                uint2 b = bb[nt * 32];
                mma_f16(acc[nt], a0, a1, a2, a3, b.x, b.y);
            }
        }
        __syncthreads();
        if (c + 2 < NCH) { stage(c + 2, buf); CP_COMMIT(); }
        else             { CP_COMMIT(); }
    }

    zp0 += __shfl_xor_sync(0xffffffffu, zp0, 1);
    zp0 += __shfl_xor_sync(0xffffffffu, zp0, 2);
    zp1 += __shfl_xor_sync(0xffffffffu, zp1, 1);
    zp1 += __shfl_xor_sync(0xffffffffu, zp1, 2);
    if (tig == 0) {
        g_z8[jq * Nn + i0 + ra] = zp0;
        g_z8[jq * Nn + i0 + ra + 8] = zp1;
    }

    float* ob = g_o8 + (size_t)jq * Nn * 64;
#pragma unroll
    for (int nt = 0; nt < 8; ++nt) {
        const int col = nt * 8 + tig * 2;
        *(float2*)(ob + (size_t)(i0 + ra) * 64 + col) =
            make_float2(acc[nt][0], acc[nt][1]);
        *(float2*)(ob + (size_t)(i0 + ra + 8) * 64 + col) =
            make_float2(acc[nt][2], acc[nt][3]);
    }
}

// ---------------- kernel 5: combine + normalize ----------------
__global__ __launch_bounds__(256) void k_norm(float* __restrict__ out) {
    const int idx = blockIdx.x * 256 + threadIdx.x;
    const int row = idx >> 4;
    const float4* o0 = (const float4*)g_o8;
    float4 o = make_float4(0.f, 0.f, 0.f, 0.f);
    float z = 0.f;
#pragma unroll
    for (int k = 0; k < NJQ; ++k) {
        float4 a = o0[(size_t)k * Nn * 16 + idx];
        o.x += a.x; o.y += a.y; o.z += a.z; o.w += a.w;
        z += g_z8[k * Nn + row];
    }
    float zi = 1.0f / z;
    o.x *= zi; o.y *= zi; o.z *= zi; o.w *= zi;
    ((float4*)out)[idx] = o;
}

// ---------------- launch ----------------
extern "C" void kernel_launch(void* const* d_in, const int* in_sizes, int n_in,
                              void* d_out, int out_size) {
    const float* input = (const float*)d_in[0];
    const int*   adj   = (const int*)d_in[1];
    const float* Wm    = (const float*)d_in[2];
    const float* av    = (const float*)d_in[3];
    float* out = (float*)d_out;

    cudaFuncSetAttribute(k_attn, cudaFuncAttributeMaxDynamicSharedMemorySize, SM_TOT);

    k_packproj<<<2560, 256>>>(input, Wm, adj);
    k_scores<<<Nn / 8, 256>>>(av);
    k_prep<<<Nn / 64, 256>>>();
    k_attn<<<512, 256, SM_TOT>>>();
    k_norm<<<512, 256>>>(out);
}